// round 7
// baseline (speedup 1.0000x reference)
#include <cuda_runtime.h>
#include <cuda_fp16.h>
#include <cstdint>

#define BB 8
#define TT 2048
#define DD 1024
#define MT (BB * TT)   // 16384 rows

// ---------------- scratch (__device__ globals; no allocs allowed) -----------
__device__ float g_q[(size_t)MT * DD];
__device__ float g_k[(size_t)MT * DD];
__device__ float g_v[(size_t)MT * DD];
__device__ __half g_xhi[(size_t)MT * DD];
__device__ __half g_xlo[(size_t)MT * DD];
__device__ __half g_whi[3][(size_t)DD * DD];   // stacked q,k,v -> rows 0..3071
__device__ __half g_wlo[3][(size_t)DD * DD];
// scan intermediates
#define NCH 16
#define LCH 128
__device__ float g_finals[NCH * BB * DD];
__device__ float g_carries[NCH * BB * DD];

// ---------------- helpers ----------------------------------------------------
__device__ __forceinline__ uint32_t smem_to_u32(const void* p) {
    uint32_t a;
    asm("{ .reg .u64 t; cvta.to.shared.u64 t, %1; cvt.u32.u64 %0, t; }"
        : "=r"(a) : "l"(p));
    return a;
}
__device__ __forceinline__ void cp_async16(uint32_t saddr, const void* gptr) {
    asm volatile("cp.async.cg.shared.global [%0], [%1], 16;\n"
                 :: "r"(saddr), "l"(gptr));
}
__device__ __forceinline__ void cp_commit() {
    asm volatile("cp.async.commit_group;\n" ::: "memory");
}
__device__ __forceinline__ void cp_wait1() {
    asm volatile("cp.async.wait_group 1;\n" ::: "memory");
}
__device__ __forceinline__ void cp_wait0() {
    asm volatile("cp.async.wait_group 0;\n" ::: "memory");
}
__device__ __forceinline__ void ldm_x4(uint32_t* r, uint32_t addr) {
    asm volatile("ldmatrix.sync.aligned.m8n8.x4.shared.b16 {%0,%1,%2,%3}, [%4];"
                 : "=r"(r[0]), "=r"(r[1]), "=r"(r[2]), "=r"(r[3]) : "r"(addr));
}
// fp16 MMA, fp32 accumulate (main hh term)
__device__ __forceinline__ void mma_f32acc(float* c, const uint32_t* a, const uint32_t* b) {
    asm volatile("mma.sync.aligned.m16n8k16.row.col.f32.f16.f16.f32 "
                 "{%0,%1,%2,%3}, {%4,%5,%6,%7}, {%8,%9}, {%0,%1,%2,%3};"
                 : "+f"(c[0]), "+f"(c[1]), "+f"(c[2]), "+f"(c[3])
                 : "r"(a[0]), "r"(a[1]), "r"(a[2]), "r"(a[3]),
                   "r"(b[0]), "r"(b[1]));
}
// fp16 MMA, fp16 accumulate (small cross terms)
__device__ __forceinline__ void mma_f16acc(uint32_t* c, const uint32_t* a, const uint32_t* b) {
    asm volatile("mma.sync.aligned.m16n8k16.row.col.f16.f16.f16.f16 "
                 "{%0,%1}, {%2,%3,%4,%5}, {%6,%7}, {%0,%1};"
                 : "+r"(c[0]), "+r"(c[1])
                 : "r"(a[0]), "r"(a[1]), "r"(a[2]), "r"(a[3]),
                   "r"(b[0]), "r"(b[1]));
}

// ---------------- split fp32 -> fp16 hi/lo ----------------------------------
__global__ __launch_bounds__(256) void split_kernel(const float* __restrict__ src,
                                                    __half* __restrict__ hi,
                                                    __half* __restrict__ lo,
                                                    int n4) {
    int i = blockIdx.x * blockDim.x + threadIdx.x;
    if (i >= n4) return;
    float4 v = ((const float4*)src)[i];
    __half h[4], l[4];
    float f[4] = {v.x, v.y, v.z, v.w};
#pragma unroll
    for (int j = 0; j < 4; j++) {
        h[j] = __float2half_rn(f[j]);
        l[j] = __float2half_rn(f[j] - __half2float(h[j]));
    }
    ((uint2*)hi)[i] = *(uint2*)h;
    ((uint2*)lo)[i] = *(uint2*)l;
}

// ---------------- fused QKV fp16 split GEMM ----------------------------------
// C_seg[M,1024] = (Ahi+Alo)[M,K] @ (Whi+Wlo)[3072,K]^T + bias_seg
// hh -> f32 accum; hl + lh -> shared f16 accum.
// Block tile 128x128, BK=32, 8 warps (2m x 4n), warp tile 64x32.
#define ASTR 40                    // padded row stride in f16 elements
#define ROWB (ASTR * 2)            // 80 bytes
#define ST_A_HI 0
#define ST_A_LO (128 * ROWB)               // 10240
#define ST_B_HI (2 * 128 * ROWB)           // 20480
#define ST_B_LO (3 * 128 * ROWB)           // 30720
#define STAGE_B (4 * 128 * ROWB)           // 40960
#define NSTAGE 3
#define NCHK (DD / 32)             // 32 chunks

__global__ __launch_bounds__(256, 1) void gemm_qkv_kernel(
    const __half* __restrict__ Ahi, const __half* __restrict__ Alo,
    const __half* __restrict__ Whi, const __half* __restrict__ Wlo,
    const float* __restrict__ bq, const float* __restrict__ bk,
    const float* __restrict__ bv,
    float* __restrict__ Cq, float* __restrict__ Ck, float* __restrict__ Cv) {
    extern __shared__ char smem[];
    const uint32_t smem_base = smem_to_u32(smem);
    const int tid = threadIdx.x;
    const int wid = tid >> 5;
    const int lane = tid & 31;
    const int warp_m = wid & 1;          // 2 warps in M (64 rows each)
    const int warp_n = wid >> 1;         // 4 warps in N (32 cols each)
    const int bm = blockIdx.y * 128;
    const int bn = blockIdx.x * 128;     // 0..3071 within stacked W
    const int seg = bn >> 10;            // 0=q, 1=k, 2=v
    const int cn = bn & (DD - 1);        // column base within segment

    const float* bias = (seg == 0) ? bq : (seg == 1) ? bk : bv;
    float* C = (seg == 0) ? Cq : (seg == 1) ? Ck : Cv;

    // ldmatrix lane-address components
    const int lr = lane & 7;
    const int g = lane >> 3;                       // 0..3
    const uint32_t a_row = warp_m * 64 + (g & 1) * 8 + lr;   // + mt*16
    const uint32_t a_koff = (g >> 1) * 8;
    const uint32_t b_row = warp_n * 32 + ((lane >> 4) << 3) + lr;  // + j*16
    const uint32_t b_koff = ((lane >> 3) & 1) * 8;

    float acc32[4][4][4];
    uint32_t acc16[4][4][2];
#pragma unroll
    for (int i = 0; i < 4; i++)
#pragma unroll
        for (int j = 0; j < 4; j++) {
#pragma unroll
            for (int r = 0; r < 4; r++) acc32[i][j][r] = 0.f;
            acc16[i][j][0] = 0u;
            acc16[i][j][1] = 0u;
        }

    // ---- async tile loader: 4 tiles x 128 rows x 4 x 16B segs ---------------
    auto issue_load = [&](int ch) {
        const uint32_t sbase = smem_base + (ch % NSTAGE) * STAGE_B;
        const int k0 = ch * 32;
        const __half* s0 = Ahi + (size_t)bm * DD + k0;
        const __half* s1 = Alo + (size_t)bm * DD + k0;
        const __half* s2 = Whi + (size_t)bn * DD + k0;
        const __half* s3 = Wlo + (size_t)bn * DD + k0;
#pragma unroll
        for (int rep = 0; rep < 2; rep++) {
            const int idx = tid + rep * 256;        // 0..511
            const int r = idx >> 2, segi = idx & 3;
            const uint32_t soff = r * ROWB + segi * 16;
            const size_t goff = (size_t)r * DD + segi * 8;
            cp_async16(sbase + ST_A_HI + soff, s0 + goff);
            cp_async16(sbase + ST_A_LO + soff, s1 + goff);
            cp_async16(sbase + ST_B_HI + soff, s2 + goff);
            cp_async16(sbase + ST_B_LO + soff, s3 + goff);
        }
        cp_commit();
    };

    issue_load(0);
    issue_load(1);

    for (int ch = 0; ch < NCHK; ch++) {
        if (ch == NCHK - 1) cp_wait0(); else cp_wait1();
        __syncthreads();
        if (ch + 2 < NCHK) issue_load(ch + 2);

        const uint32_t base = smem_base + (ch % NSTAGE) * STAGE_B;
#pragma unroll
        for (int ks = 0; ks < 2; ks++) {
            uint32_t ahi[4][4], alo[4][4], bhi[2][4], blo[2][4];
#pragma unroll
            for (int mt = 0; mt < 4; mt++) {
                uint32_t ar = base + (a_row + mt * 16) * ROWB
                            + (ks * 16 + a_koff) * 2;
                ldm_x4(ahi[mt], ar + ST_A_HI);
                ldm_x4(alo[mt], ar + ST_A_LO);
            }
#pragma unroll
            for (int j = 0; j < 2; j++) {             // each covers 2 n-tiles
                uint32_t br = base + (b_row + j * 16) * ROWB
                            + (ks * 16 + b_koff) * 2;
                ldm_x4(bhi[j], br + ST_B_HI);
                ldm_x4(blo[j], br + ST_B_LO);
            }
#pragma unroll
            for (int mt = 0; mt < 4; mt++)
#pragma unroll
                for (int nt = 0; nt < 4; nt++) {
                    const uint32_t* bh = &bhi[nt >> 1][(nt & 1) * 2];
                    const uint32_t* bl = &blo[nt >> 1][(nt & 1) * 2];
                    mma_f32acc(acc32[mt][nt], ahi[mt], bh);
                    mma_f16acc(acc16[mt][nt], ahi[mt], bl);
                    mma_f16acc(acc16[mt][nt], alo[mt], bh);
                }
        }
    }

    // ---- epilogue: acc32 + acc16 + bias, direct frag stores -----------------
    const int qr = lane >> 2;           // 0..7
    const int qc = (lane & 3) * 2;      // 0,2,4,6
#pragma unroll
    for (int mt = 0; mt < 4; mt++) {
#pragma unroll
        for (int nt = 0; nt < 4; nt++) {
            const int row0 = bm + warp_m * 64 + mt * 16 + qr;
            const int col = cn + warp_n * 32 + nt * 8 + qc;
            const float2 bvv = *(const float2*)&bias[col];
            const float2 x0 = __half22float2(*(__half2*)&acc16[mt][nt][0]);
            const float2 x1 = __half22float2(*(__half2*)&acc16[mt][nt][1]);
            float2 v0, v1;
            v0.x = acc32[mt][nt][0] + x0.x + bvv.x;
            v0.y = acc32[mt][nt][1] + x0.y + bvv.y;
            v1.x = acc32[mt][nt][2] + x1.x + bvv.x;
            v1.y = acc32[mt][nt][3] + x1.y + bvv.y;
            *(float2*)&C[(size_t)row0 * DD + col] = v0;
            *(float2*)&C[(size_t)(row0 + 8) * DD + col] = v1;
        }
    }
}

// ---------------- chunked scan (kv = k*v computed inline) --------------------
__global__ __launch_bounds__(256) void scan1_kernel(const float* __restrict__ decay) {
    int x = blockIdx.x * blockDim.x + threadIdx.x;   // < NCH*BB*DD
    int d = x & (DD - 1);
    int b = (x >> 10) & (BB - 1);
    int c = x >> 13;
    float dec = decay[d];
    size_t base = (size_t)b * TT * DD + (size_t)c * LCH * DD + d;
    float mem = 0.f;
#pragma unroll 4
    for (int t = 0; t < LCH; t++) {
        size_t off = base + (size_t)t * DD;
        mem = fmaf(dec, mem, g_k[off] * g_v[off]);
    }
    g_finals[((size_t)c * BB + b) * DD + d] = mem;
}

__global__ __launch_bounds__(256) void scan2_kernel(const float* __restrict__ decay) {
    int x = blockIdx.x * blockDim.x + threadIdx.x;   // < BB*DD
    int d = x & (DD - 1);
    int b = x >> 10;
    float dec = decay[d];
    float pL = dec;
#pragma unroll
    for (int i = 0; i < 7; i++) pL *= pL;            // dec^128
    float carry = 0.f;
#pragma unroll
    for (int c = 0; c < NCH; c++) {
        size_t idx = ((size_t)c * BB + b) * DD + d;
        g_carries[idx] = carry;
        carry = fmaf(pL, carry, g_finals[idx]);
    }
}

__global__ __launch_bounds__(256) void scan3_kernel(const float* __restrict__ decay,
                                                    float* __restrict__ out) {
    int x = blockIdx.x * blockDim.x + threadIdx.x;
    int d = x & (DD - 1);
    int b = (x >> 10) & (BB - 1);
    int c = x >> 13;
    float dec = decay[d];
    size_t base = (size_t)b * TT * DD + (size_t)c * LCH * DD + d;
    float mem = g_carries[((size_t)c * BB + b) * DD + d];
#pragma unroll 4
    for (int t = 0; t < LCH; t++) {
        size_t off = base + (size_t)t * DD;
        mem = fmaf(dec, mem, g_k[off] * g_v[off]);
        out[off] = g_q[off] * mem;
    }
}

// ---------------- launch -----------------------------------------------------
extern "C" void kernel_launch(void* const* d_in, const int* in_sizes, int n_in,
                              void* d_out, int out_size) {
    const float* x     = (const float*)d_in[0];
    const float* Wq    = (const float*)d_in[1];
    const float* bq    = (const float*)d_in[2];
    const float* Wk    = (const float*)d_in[3];
    const float* bk    = (const float*)d_in[4];
    const float* Wv    = (const float*)d_in[5];
    const float* bv    = (const float*)d_in[6];
    const float* decay = (const float*)d_in[7];
    float* out = (float*)d_out;

    float *q_p, *k_p, *v_p;
    __half *xhi_p, *xlo_p, *whi_p, *wlo_p;
    cudaGetSymbolAddress((void**)&q_p, g_q);
    cudaGetSymbolAddress((void**)&k_p, g_k);
    cudaGetSymbolAddress((void**)&v_p, g_v);
    cudaGetSymbolAddress((void**)&xhi_p, g_xhi);
    cudaGetSymbolAddress((void**)&xlo_p, g_xlo);
    cudaGetSymbolAddress((void**)&whi_p, g_whi);
    cudaGetSymbolAddress((void**)&wlo_p, g_wlo);

    const size_t WN = (size_t)DD * DD;

    // hi/lo splits
    split_kernel<<<(MT * DD / 4) / 256, 256>>>(x, xhi_p, xlo_p, MT * DD / 4);
    split_kernel<<<(int)(WN / 4) / 256, 256>>>(Wq, whi_p + 0 * WN, wlo_p + 0 * WN, (int)(WN / 4));
    split_kernel<<<(int)(WN / 4) / 256, 256>>>(Wk, whi_p + 1 * WN, wlo_p + 1 * WN, (int)(WN / 4));
    split_kernel<<<(int)(WN / 4) / 256, 256>>>(Wv, whi_p + 2 * WN, wlo_p + 2 * WN, (int)(WN / 4));

    // fused QKV HMMA GEMM (single launch, N=3072)
    const int smem_bytes = NSTAGE * STAGE_B;   // 122880
    cudaFuncSetAttribute(gemm_qkv_kernel, cudaFuncAttributeMaxDynamicSharedMemorySize, smem_bytes);
    dim3 grid(3 * DD / 128, MT / 128);         // (24, 128) = 3072 CTAs
    gemm_qkv_kernel<<<grid, 256, smem_bytes>>>(xhi_p, xlo_p, whi_p, wlo_p,
                                               bq, bk, bv, q_p, k_p, v_p);

    // chunked scan
    scan1_kernel<<<(NCH * BB * DD) / 256, 256>>>(decay);
    scan2_kernel<<<(BB * DD) / 256, 256>>>(decay);
    scan3_kernel<<<(NCH * BB * DD) / 256, 256>>>(decay, out);
}

// round 10
// speedup vs baseline: 1.0718x; 1.0718x over previous
#include <cuda_runtime.h>
#include <cuda_bf16.h>
#include <cstdint>

#define BB 8
#define TT 2048
#define DD 1024
#define MT (BB * TT)   // 16384 rows

// ---------------- scratch (__device__ globals; no allocs allowed) -----------
__device__ float g_q[(size_t)MT * DD];
__device__ float g_k[(size_t)MT * DD];
__device__ float g_v[(size_t)MT * DD];
__device__ __nv_bfloat16 g_xhi[(size_t)MT * DD];
__device__ __nv_bfloat16 g_xlo[(size_t)MT * DD];
__device__ __nv_bfloat16 g_whi[3][(size_t)DD * DD];   // stacked q,k,v -> rows 0..3071
__device__ __nv_bfloat16 g_wlo[3][(size_t)DD * DD];
// scan intermediates
#define NCH 16
#define LCH 128
__device__ float g_finals[NCH * BB * DD];
__device__ float g_carries[NCH * BB * DD];

// ---------------- helpers ----------------------------------------------------
__device__ __forceinline__ uint32_t smem_to_u32(const void* p) {
    uint32_t a;
    asm("{ .reg .u64 t; cvta.to.shared.u64 t, %1; cvt.u32.u64 %0, t; }"
        : "=r"(a) : "l"(p));
    return a;
}
__device__ __forceinline__ void cp_async16(uint32_t saddr, const void* gptr) {
    asm volatile("cp.async.cg.shared.global [%0], [%1], 16;\n"
                 :: "r"(saddr), "l"(gptr));
}
__device__ __forceinline__ void cp_commit() {
    asm volatile("cp.async.commit_group;\n" ::: "memory");
}
__device__ __forceinline__ void cp_wait1() {
    asm volatile("cp.async.wait_group 1;\n" ::: "memory");
}
__device__ __forceinline__ void cp_wait0() {
    asm volatile("cp.async.wait_group 0;\n" ::: "memory");
}
__device__ __forceinline__ void ldm_x4(uint32_t* r, uint32_t addr) {
    asm volatile("ldmatrix.sync.aligned.m8n8.x4.shared.b16 {%0,%1,%2,%3}, [%4];"
                 : "=r"(r[0]), "=r"(r[1]), "=r"(r[2]), "=r"(r[3]) : "r"(addr));
}
__device__ __forceinline__ void mma_bf16(float* c, const uint32_t* a, const uint32_t* b) {
    asm volatile("mma.sync.aligned.m16n8k16.row.col.f32.bf16.bf16.f32 "
                 "{%0,%1,%2,%3}, {%4,%5,%6,%7}, {%8,%9}, {%0,%1,%2,%3};"
                 : "+f"(c[0]), "+f"(c[1]), "+f"(c[2]), "+f"(c[3])
                 : "r"(a[0]), "r"(a[1]), "r"(a[2]), "r"(a[3]),
                   "r"(b[0]), "r"(b[1]));
}

// ---------------- split fp32 -> bf16 hi/lo ----------------------------------
__global__ __launch_bounds__(256) void split_kernel(const float* __restrict__ src,
                                                    __nv_bfloat16* __restrict__ hi,
                                                    __nv_bfloat16* __restrict__ lo,
                                                    int n4) {
    int i = blockIdx.x * blockDim.x + threadIdx.x;
    if (i >= n4) return;
    float4 v = ((const float4*)src)[i];
    __nv_bfloat16 h[4], l[4];
    float f[4] = {v.x, v.y, v.z, v.w};
#pragma unroll
    for (int j = 0; j < 4; j++) {
        h[j] = __float2bfloat16_rn(f[j]);
        l[j] = __float2bfloat16_rn(f[j] - __bfloat162float(h[j]));
    }
    ((uint2*)hi)[i] = *(uint2*)h;
    ((uint2*)lo)[i] = *(uint2*)l;
}

// ---------------- fused QKV HMMA bf16 split GEMM -----------------------------
// C_seg[M,1024] = (Ahi+Alo)[M,K] @ (Whi+Wlo)[3072,K]^T (3 terms) + bias_seg
// Block tile 128x256, BK=32, 8 warps (2m x 4n), warp tile 64x64.
// Term loop hoisted outermost: 32 independent MMAs between same-acc reuses.
#define ASTR 40                    // padded row stride in bf16 elements
#define ROWB (ASTR * 2)            // 80 bytes
#define ST_A_HI 0
#define ST_A_LO (128 * ROWB)               // 10240
#define ST_B_HI (2 * 128 * ROWB)           // 20480
#define ST_B_LO (ST_B_HI + 256 * ROWB)     // 40960
#define STAGE_B (ST_B_LO + 256 * ROWB)     // 61440
#define NSTAGE 3
#define NCHK (DD / 32)             // 32 chunks

__global__ __launch_bounds__(256, 1) void gemm_qkv_kernel(
    const __nv_bfloat16* __restrict__ Ahi, const __nv_bfloat16* __restrict__ Alo,
    const __nv_bfloat16* __restrict__ Whi, const __nv_bfloat16* __restrict__ Wlo,
    const float* __restrict__ bq, const float* __restrict__ bk,
    const float* __restrict__ bv,
    float* __restrict__ Cq, float* __restrict__ Ck, float* __restrict__ Cv) {
    extern __shared__ char smem[];
    const uint32_t smem_base = smem_to_u32(smem);
    const int tid = threadIdx.x;
    const int wid = tid >> 5;
    const int lane = tid & 31;
    const int warp_m = wid & 1;          // 2 warps in M (64 rows each)
    const int warp_n = wid >> 1;         // 4 warps in N (64 cols each)
    const int bm = blockIdx.y * 128;
    const int bn = blockIdx.x * 256;     // 0..3071 within stacked W
    const int seg = bn >> 10;            // 0=q, 1=k, 2=v
    const int cn = bn & (DD - 1);        // column base within segment

    const float* bias = (seg == 0) ? bq : (seg == 1) ? bk : bv;
    float* C = (seg == 0) ? Cq : (seg == 1) ? Ck : Cv;

    // ldmatrix lane-address components
    const int lr = lane & 7;
    const int g = lane >> 3;                       // 0..3
    const uint32_t a_row = warp_m * 64 + (g & 1) * 8 + lr;   // + mt*16
    const uint32_t a_koff = (g >> 1) * 8;
    const uint32_t b_row = warp_n * 64 + ((lane >> 4) << 3) + lr;  // + j*16
    const uint32_t b_koff = ((lane >> 3) & 1) * 8;

    float acc[4][8][4];
#pragma unroll
    for (int i = 0; i < 4; i++)
#pragma unroll
        for (int j = 0; j < 8; j++)
#pragma unroll
            for (int r = 0; r < 4; r++) acc[i][j][r] = 0.f;

    // ---- async tile loader -------------------------------------------------
    auto issue_load = [&](int ch) {
        const uint32_t sbase = smem_base + (ch % NSTAGE) * STAGE_B;
        const int k0 = ch * 32;
        {
            const __nv_bfloat16* sh = Ahi + (size_t)bm * DD + k0;
            const __nv_bfloat16* sl = Alo + (size_t)bm * DD + k0;
#pragma unroll
            for (int rep = 0; rep < 2; rep++) {
                const int idx = tid + rep * 256;        // 0..511
                const int r = idx >> 2, segi = idx & 3;
                cp_async16(sbase + ST_A_HI + r * ROWB + segi * 16,
                           sh + (size_t)r * DD + segi * 8);
                cp_async16(sbase + ST_A_LO + r * ROWB + segi * 16,
                           sl + (size_t)r * DD + segi * 8);
            }
        }
        {
            const __nv_bfloat16* sh = Whi + (size_t)bn * DD + k0;
            const __nv_bfloat16* sl = Wlo + (size_t)bn * DD + k0;
#pragma unroll
            for (int rep = 0; rep < 4; rep++) {
                const int idx = tid + rep * 256;        // 0..1023
                const int r = idx >> 2, segi = idx & 3;
                cp_async16(sbase + ST_B_HI + r * ROWB + segi * 16,
                           sh + (size_t)r * DD + segi * 8);
                cp_async16(sbase + ST_B_LO + r * ROWB + segi * 16,
                           sl + (size_t)r * DD + segi * 8);
            }
        }
        cp_commit();
    };

    issue_load(0);
    issue_load(1);

    for (int ch = 0; ch < NCHK; ch++) {
        if (ch == NCHK - 1) cp_wait0(); else cp_wait1();
        __syncthreads();
        if (ch + 2 < NCHK) issue_load(ch + 2);

        const uint32_t base = smem_base + (ch % NSTAGE) * STAGE_B;
#pragma unroll
        for (int ks = 0; ks < 2; ks++) {
            uint32_t ahi[4][4], alo[4][4], bhi[4][4], blo[4][4];
#pragma unroll
            for (int mt = 0; mt < 4; mt++) {
                uint32_t ar = base + (a_row + mt * 16) * ROWB
                            + (ks * 16 + a_koff) * 2;
                ldm_x4(ahi[mt], ar + ST_A_HI);
                ldm_x4(alo[mt], ar + ST_A_LO);
            }
#pragma unroll
            for (int j = 0; j < 4; j++) {             // each covers 2 n-tiles
                uint32_t br = base + (b_row + j * 16) * ROWB
                            + (ks * 16 + b_koff) * 2;
                ldm_x4(bhi[j], br + ST_B_HI);
                ldm_x4(blo[j], br + ST_B_LO);
            }
            // term-outer order: 32 independent MMAs between same-acc reuses
#pragma unroll
            for (int mt = 0; mt < 4; mt++)
#pragma unroll
                for (int nt = 0; nt < 8; nt++)
                    mma_bf16(acc[mt][nt], ahi[mt], &bhi[nt >> 1][(nt & 1) * 2]);
#pragma unroll
            for (int mt = 0; mt < 4; mt++)
#pragma unroll
                for (int nt = 0; nt < 8; nt++)
                    mma_bf16(acc[mt][nt], ahi[mt], &blo[nt >> 1][(nt & 1) * 2]);
#pragma unroll
            for (int mt = 0; mt < 4; mt++)
#pragma unroll
                for (int nt = 0; nt < 8; nt++)
                    mma_bf16(acc[mt][nt], alo[mt], &bhi[nt >> 1][(nt & 1) * 2]);
        }
    }

    // ---- epilogue: direct frag stores + bias --------------------------------
    const int qr = lane >> 2;           // 0..7
    const int qc = (lane & 3) * 2;      // 0,2,4,6
#pragma unroll
    for (int mt = 0; mt < 4; mt++) {
#pragma unroll
        for (int nt = 0; nt < 8; nt++) {
            const int row0 = bm + warp_m * 64 + mt * 16 + qr;
            const int col = cn + warp_n * 64 + nt * 8 + qc;
            const float2 bvv = *(const float2*)&bias[col];
            float2 v0, v1;
            v0.x = acc[mt][nt][0] + bvv.x;
            v0.y = acc[mt][nt][1] + bvv.y;
            v1.x = acc[mt][nt][2] + bvv.x;
            v1.y = acc[mt][nt][3] + bvv.y;
            *(float2*)&C[(size_t)row0 * DD + col] = v0;
            *(float2*)&C[(size_t)(row0 + 8) * DD + col] = v1;
        }
    }
}

// ---------------- chunked scan (kv = k*v computed inline) --------------------
__global__ __launch_bounds__(256) void scan1_kernel(const float* __restrict__ decay) {
    int x = blockIdx.x * blockDim.x + threadIdx.x;   // < NCH*BB*DD
    int d = x & (DD - 1);
    int b = (x >> 10) & (BB - 1);
    int c = x >> 13;
    float dec = decay[d];
    size_t base = (size_t)b * TT * DD + (size_t)c * LCH * DD + d;
    float mem = 0.f;
#pragma unroll 4
    for (int t = 0; t < LCH; t++) {
        size_t off = base + (size_t)t * DD;
        mem = fmaf(dec, mem, g_k[off] * g_v[off]);
    }
    g_finals[((size_t)c * BB + b) * DD + d] = mem;
}

__global__ __launch_bounds__(256) void scan2_kernel(const float* __restrict__ decay) {
    int x = blockIdx.x * blockDim.x + threadIdx.x;   // < BB*DD
    int d = x & (DD - 1);
    int b = x >> 10;
    float dec = decay[d];
    float pL = dec;
#pragma unroll
    for (int i = 0; i < 7; i++) pL *= pL;            // dec^128
    float carry = 0.f;
#pragma unroll
    for (int c = 0; c < NCH; c++) {
        size_t idx = ((size_t)c * BB + b) * DD + d;
        g_carries[idx] = carry;
        carry = fmaf(pL, carry, g_finals[idx]);
    }
}

__global__ __launch_bounds__(256) void scan3_kernel(const float* __restrict__ decay,
                                                    float* __restrict__ out) {
    int x = blockIdx.x * blockDim.x + threadIdx.x;
    int d = x & (DD - 1);
    int b = (x >> 10) & (BB - 1);
    int c = x >> 13;
    float dec = decay[d];
    size_t base = (size_t)b * TT * DD + (size_t)c * LCH * DD + d;
    float mem = g_carries[((size_t)c * BB + b) * DD + d];
#pragma unroll 4
    for (int t = 0; t < LCH; t++) {
        size_t off = base + (size_t)t * DD;
        mem = fmaf(dec, mem, g_k[off] * g_v[off]);
        out[off] = g_q[off] * mem;
    }
}

// ---------------- launch -----------------------------------------------------
extern "C" void kernel_launch(void* const* d_in, const int* in_sizes, int n_in,
                              void* d_out, int out_size) {
    const float* x     = (const float*)d_in[0];
    const float* Wq    = (const float*)d_in[1];
    const float* bq    = (const float*)d_in[2];
    const float* Wk    = (const float*)d_in[3];
    const float* bk    = (const float*)d_in[4];
    const float* Wv    = (const float*)d_in[5];
    const float* bv    = (const float*)d_in[6];
    const float* decay = (const float*)d_in[7];
    float* out = (float*)d_out;

    float *q_p, *k_p, *v_p;
    __nv_bfloat16 *xhi_p, *xlo_p, *whi_p, *wlo_p;
    cudaGetSymbolAddress((void**)&q_p, g_q);
    cudaGetSymbolAddress((void**)&k_p, g_k);
    cudaGetSymbolAddress((void**)&v_p, g_v);
    cudaGetSymbolAddress((void**)&xhi_p, g_xhi);
    cudaGetSymbolAddress((void**)&xlo_p, g_xlo);
    cudaGetSymbolAddress((void**)&whi_p, g_whi);
    cudaGetSymbolAddress((void**)&wlo_p, g_wlo);

    const size_t WN = (size_t)DD * DD;

    // hi/lo splits
    split_kernel<<<(MT * DD / 4) / 256, 256>>>(x, xhi_p, xlo_p, MT * DD / 4);
    split_kernel<<<(int)(WN / 4) / 256, 256>>>(Wq, whi_p + 0 * WN, wlo_p + 0 * WN, (int)(WN / 4));
    split_kernel<<<(int)(WN / 4) / 256, 256>>>(Wk, whi_p + 1 * WN, wlo_p + 1 * WN, (int)(WN / 4));
    split_kernel<<<(int)(WN / 4) / 256, 256>>>(Wv, whi_p + 2 * WN, wlo_p + 2 * WN, (int)(WN / 4));

    // fused QKV HMMA GEMM (single launch, N=3072)
    const int smem_bytes = NSTAGE * STAGE_B;   // 184320
    cudaFuncSetAttribute(gemm_qkv_kernel, cudaFuncAttributeMaxDynamicSharedMemorySize, smem_bytes);
    dim3 grid(3 * DD / 256, MT / 128);         // (12, 128) = 1536 CTAs
    gemm_qkv_kernel<<<grid, 256, smem_bytes>>>(xhi_p, xlo_p, whi_p, wlo_p,
                                               bq, bk, bv, q_p, k_p, v_p);

    // chunked scan
    scan1_kernel<<<(NCH * BB * DD) / 256, 256>>>(decay);
    scan2_kernel<<<(BB * DD) / 256, 256>>>(decay);
    scan3_kernel<<<(NCH * BB * DD) / 256, 256>>>(decay, out);
}